// round 10
// baseline (speedup 1.0000x reference)
#include <cuda_runtime.h>
#include <cuda_fp16.h>
#include <stdint.h>
#include <math.h>

#define NB 4
#define LT 16384
#define CD 256
#define NH 8
#define DH 32
#define FF 512
#define NLAY 4
#define MTOT (NB*LT)
#define NQKV 768

// ---- fp32 scratch ----
__device__ float g_x[MTOT*CD];
__device__ float g_tmp[MTOT*CD];
__device__ float g_KV[NB*NH*DH*DH];
__device__ float g_Ksum[NB*NH*DH];
__device__ float g_bqkv[NLAY*NQKV];
// ---- fp16 scratch ----
__device__ __half g_xh[MTOT*CD];
__device__ __half g_ah[MTOT*CD];
__device__ __half g_hh[MTOT*FF];
__device__ __half g_qkvh[MTOT*NQKV];
__device__ __half g_Wqkvh[NLAY*NQKV*CD];
__device__ __half g_Woh[NLAY*CD*CD];
__device__ __half g_W1h[NLAY*FF*CD];
__device__ __half g_W2h[NLAY*CD*FF];

__device__ __forceinline__ uint32_t smem_u32(const void* p) {
    uint32_t a;
    asm("{ .reg .u64 t; cvta.to.shared.u64 t, %1; cvt.u32.u64 %0, t; }" : "=r"(a) : "l"(p));
    return a;
}
__device__ __forceinline__ void cpa16(uint32_t saddr, const void* g) {
    asm volatile("cp.async.cg.shared.global [%0], [%1], 16;" :: "r"(saddr), "l"(g));
}
#define LDSM4(r0,r1,r2,r3,addr) \
    asm volatile("ldmatrix.sync.aligned.m8n8.x4.shared.b16 {%0,%1,%2,%3}, [%4];" \
        : "=r"(r0),"=r"(r1),"=r"(r2),"=r"(r3) : "r"(addr))
#define MMA16816(c, a, b) \
    asm volatile("mma.sync.aligned.m16n8k16.row.col.f32.f16.f16.f32 " \
        "{%0,%1,%2,%3}, {%4,%5,%6,%7}, {%8,%9}, {%0,%1,%2,%3};" \
        : "+f"((c)[0]),"+f"((c)[1]),"+f"((c)[2]),"+f"((c)[3]) \
        : "r"((a)[0]),"r"((a)[1]),"r"((a)[2]),"r"((a)[3]), "r"((b)[0]),"r"((b)[1]))

__device__ __forceinline__ void st2(float* p, float a, float b) {
    *(float2*)p = make_float2(a, b);
}
__device__ __forceinline__ void st2(__half* p, float a, float b) {
    *(__half2*)p = __floats2half2_rn(a, b);
}

// ============================================================
// HMMA f16 GEMM: C[M,N] = A[M,K] @ B[N,K]^T + bias
// ACT 0=none, 1=elu+1, 2=relu, 3=elu+1 if col<512 else none (fused QKV)
// 128x128x32 CTA tile, 8 warps (2x4), 3-stage cp.async pipeline.
// ============================================================
#define STG 16384
template<int ACT, typename OutT>
__global__ void __launch_bounds__(256)
gemm_mma(const __half* __restrict__ A, const __half* __restrict__ B,
         const float* __restrict__ bias, OutT* __restrict__ C,
         int M, int N, int K)
{
    __shared__ __align__(128) char smem[3*STG];   // 48KB: 3 stages of (A 8KB + B 8KB)
    const int tid = threadIdx.x, wid = tid >> 5, lane = tid & 31;
    const int wm = wid & 1, wn = wid >> 1;
    const int bn = blockIdx.x << 7, bm = blockIdx.y << 7;
    const uint32_t sb = smem_u32(smem);
    const __half* Ag = A + (size_t)bm * K;
    const __half* Bg = B + (size_t)bn * K;
    const int S = K >> 5;

    float acc[4][4][4];
#pragma unroll
    for (int mi = 0; mi < 4; mi++)
#pragma unroll
        for (int ni = 0; ni < 4; ni++)
#pragma unroll
            for (int j = 0; j < 4; j++) acc[mi][ni][j] = 0.f;

    auto load_st = [&](int s) {
        uint32_t dstA = sb + (uint32_t)(s % 3) * STG;
        uint32_t dstB = dstA + 8192;
        int kt = s << 5;
#pragma unroll
        for (int i = 0; i < 2; i++) {
            int c = tid + (i << 8);
            int r = c >> 2, k4 = c & 3;
            uint32_t sw = (uint32_t)(k4 ^ ((r >> 1) & 3));
            cpa16(dstA + r * 64 + (sw << 4), Ag + (size_t)r * K + kt + (k4 << 3));
            cpa16(dstB + r * 64 + (sw << 4), Bg + (size_t)r * K + kt + (k4 << 3));
        }
        asm volatile("cp.async.commit_group;" ::: "memory");
    };

    load_st(0);
    if (S > 1) load_st(1);

    for (int s = 0; s < S; s++) {
        if (s + 1 < S) asm volatile("cp.async.wait_group 1;" ::: "memory");
        else           asm volatile("cp.async.wait_group 0;" ::: "memory");
        __syncthreads();
        if (s + 2 < S) load_st(s + 2);

        uint32_t bA = sb + (uint32_t)(s % 3) * STG;
        uint32_t bB = bA + 8192;
#pragma unroll
        for (int ks = 0; ks < 2; ks++) {
            uint32_t af[4][4], bf[4][2];
#pragma unroll
            for (int mi = 0; mi < 4; mi++) {
                int r = wm * 64 + mi * 16 + (lane & 15);
                int ch = (ks << 1) + (lane >> 4);
                uint32_t ad = bA + r * 64 + (uint32_t)((ch ^ ((r >> 1) & 3)) << 4);
                LDSM4(af[mi][0], af[mi][1], af[mi][2], af[mi][3], ad);
            }
#pragma unroll
            for (int pr = 0; pr < 2; pr++) {
                int n = wn * 32 + pr * 16 + ((lane >> 4) << 3) + (lane & 7);
                int ch = (ks << 1) + ((lane >> 3) & 1);
                uint32_t bd = bB + n * 64 + (uint32_t)((ch ^ ((n >> 1) & 3)) << 4);
                LDSM4(bf[2*pr][0], bf[2*pr][1], bf[2*pr+1][0], bf[2*pr+1][1], bd);
            }
#pragma unroll
            for (int mi = 0; mi < 4; mi++)
#pragma unroll
                for (int ni = 0; ni < 4; ni++)
                    MMA16816(acc[mi][ni], af[mi], bf[ni]);
        }
    }

    // epilogue
    int g = lane >> 2, tg = lane & 3;
#pragma unroll
    for (int ni = 0; ni < 4; ni++) {
        int col = bn + wn * 32 + ni * 8 + tg * 2;
        float b0 = bias[col], b1 = bias[col + 1];
        bool doact1 = (ACT == 1) || (ACT == 3 && col < 512);
#pragma unroll
        for (int mi = 0; mi < 4; mi++) {
            int r0 = bm + wm * 64 + mi * 16 + g;
            float v00 = acc[mi][ni][0] + b0, v01 = acc[mi][ni][1] + b1;
            float v10 = acc[mi][ni][2] + b0, v11 = acc[mi][ni][3] + b1;
            if (doact1) {
                v00 = (v00 > 0.f) ? (v00 + 1.f) : expf(v00);
                v01 = (v01 > 0.f) ? (v01 + 1.f) : expf(v01);
                v10 = (v10 > 0.f) ? (v10 + 1.f) : expf(v10);
                v11 = (v11 > 0.f) ? (v11 + 1.f) : expf(v11);
            }
            if (ACT == 2) {
                v00 = fmaxf(v00, 0.f); v01 = fmaxf(v01, 0.f);
                v10 = fmaxf(v10, 0.f); v11 = fmaxf(v11, 0.f);
            }
            st2(C + (size_t)r0 * N + col, v00, v01);
            st2(C + (size_t)(r0 + 8) * N + col, v10, v11);
        }
    }
}

// ============================================================
// one-shot weight conversion + QKV concat + bias concat
// ============================================================
__global__ void wconv(const float* __restrict__ Wq, const float* __restrict__ Wk,
                      const float* __restrict__ Wv, const float* __restrict__ Wo,
                      const float* __restrict__ W1, const float* __restrict__ W2,
                      const float* __restrict__ bq, const float* __restrict__ bk,
                      const float* __restrict__ bv,
                      __half* __restrict__ Wqkv, __half* __restrict__ Woh,
                      __half* __restrict__ W1h, __half* __restrict__ W2h,
                      float* __restrict__ bqkv)
{
    const int R0 = NLAY*NQKV*CD/4;
    const int R1 = R0 + NLAY*CD*CD/4;
    const int R2 = R1 + NLAY*FF*CD/4;
    const int R3 = R2 + NLAY*CD*FF/4;
    const int R4 = R3 + NLAY*NQKV/4;
    int i4 = blockIdx.x * blockDim.x + threadIdx.x;
    if (i4 >= R4) return;
    if (i4 < R3) {
        float4 f;
        __half* dst;
        if (i4 < R0) {
            int e = i4 * 4;
            int l = e / (NQKV*CD);
            int rem = e - l*(NQKV*CD);
            int r = rem / CD, c = rem - r*CD;
            const float* W = (r < CD) ? Wq : (r < 2*CD) ? Wk : Wv;
            f = *(const float4*)(W + (size_t)l*CD*CD + (r % CD)*CD + c);
            dst = Wqkv + e;
        } else if (i4 < R1) {
            int e = (i4 - R0) * 4;
            f = *(const float4*)(Wo + e);
            dst = Woh + e;
        } else if (i4 < R2) {
            int e = (i4 - R1) * 4;
            f = *(const float4*)(W1 + e);
            dst = W1h + e;
        } else {
            int e = (i4 - R2) * 4;
            f = *(const float4*)(W2 + e);
            dst = W2h + e;
        }
        __half2 a = __floats2half2_rn(f.x, f.y), b = __floats2half2_rn(f.z, f.w);
        uint2 u; u.x = *(uint32_t*)&a; u.y = *(uint32_t*)&b;
        *(uint2*)dst = u;
    } else {
        int e = (i4 - R3) * 4;
        int l = e / NQKV;
        int r = e - l*NQKV;
        const float* B = (r < CD) ? bq : (r < 2*CD) ? bk : bv;
        *(float4*)(bqkv + e) = *(const float4*)(B + l*CD + (r % CD));
    }
}

// input transpose [CD x LT] -> x [LT x CD] (fp32) + xh (fp16)
__global__ void transpose_in(const float* __restrict__ in, float* __restrict__ out,
                             __half* __restrict__ outh) {
    __shared__ float tile[32][33];
    int bx = blockIdx.x * 32;   // over LT
    int by = blockIdx.y * 32;   // over CD
    int x = bx + threadIdx.x;
#pragma unroll
    for (int j = 0; j < 32; j += 8)
        tile[threadIdx.y + j][threadIdx.x] = in[(size_t)(by + threadIdx.y + j) * LT + x];
    __syncthreads();
    int x2 = by + threadIdx.x;
#pragma unroll
    for (int j = 0; j < 32; j += 8) {
        float v = tile[threadIdx.x][threadIdx.y + j];
        size_t o = (size_t)(bx + threadIdx.y + j) * CD + x2;
        out[o] = v;
        outh[o] = __float2half(v);
    }
}

__global__ void zero_kv() {
    int i = blockIdx.x * blockDim.x + threadIdx.x;
    if (i < NB*NH*DH*DH) g_KV[i] = 0.f;
    if (i < NB*NH*DH)    g_Ksum[i] = 0.f;
}

// KV[n,h,m,d] += sum_l K*V over 128-token chunk; fp16 qkv input [M, 768]
__global__ void kv_reduce(const __half* __restrict__ qkv) {
    __shared__ float sK[128*32];
    __shared__ float sV[128*32];
    int tid = threadIdx.x;
    int l0 = blockIdx.x * 128;
    int nh = blockIdx.y;
    int n = nh >> 3, h = nh & 7;
    const __half* Kb = qkv + (size_t)(n*LT + l0) * NQKV + 256 + h*DH;
    const __half* Vb = qkv + (size_t)(n*LT + l0) * NQKV + 512 + h*DH;
#pragma unroll
    for (int r = 0; r < 2; r++) {
        int f = tid + 256*r;          // 0..511
        int i = f >> 2;               // token 0..127
        int c8 = (f & 3) * 8;         // col group of 8
        uint4 ku = *(const uint4*)(Kb + (size_t)i*NQKV + c8);
        uint4 vu = *(const uint4*)(Vb + (size_t)i*NQKV + c8);
        const __half2* kh = (const __half2*)&ku;
        const __half2* vh = (const __half2*)&vu;
#pragma unroll
        for (int j = 0; j < 4; j++) {
            float2 kf = __half22float2(kh[j]);
            float2 vf = __half22float2(vh[j]);
            sK[i*32 + c8 + 2*j]     = kf.x;
            sK[i*32 + c8 + 2*j + 1] = kf.y;
            sV[i*32 + c8 + 2*j]     = vf.x;
            sV[i*32 + c8 + 2*j + 1] = vf.y;
        }
    }
    __syncthreads();
    float acc0=0.f, acc1=0.f, acc2=0.f, acc3=0.f;
    int e0 = tid, e1 = tid+256, e2 = tid+512, e3 = tid+768;
    int m0=e0>>5, d0=e0&31, m1=e1>>5, d1=e1&31, m2=e2>>5, d2=e2&31, m3=e3>>5, d3=e3&31;
#pragma unroll 4
    for (int i = 0; i < 128; i++) {
        const float* kr = &sK[i*32];
        const float* vr = &sV[i*32];
        acc0 += vr[m0]*kr[d0]; acc1 += vr[m1]*kr[d1];
        acc2 += vr[m2]*kr[d2]; acc3 += vr[m3]*kr[d3];
    }
    atomicAdd(&g_KV[nh*1024 + e0], acc0);
    atomicAdd(&g_KV[nh*1024 + e1], acc1);
    atomicAdd(&g_KV[nh*1024 + e2], acc2);
    atomicAdd(&g_KV[nh*1024 + e3], acc3);
    if (tid < 32) {
        float s = 0.f;
#pragma unroll 8
        for (int i = 0; i < 128; i++) s += sK[i*32 + tid];
        atomicAdd(&g_Ksum[nh*32 + tid], s);
    }
}

// attn[n,l,h,m] = Z * sum_d Q[n,l,h,d]*KV[n,h,m,d]; Q fp16 from qkv, out fp16
__global__ void attn_apply(const __half* __restrict__ qkv, __half* __restrict__ out) {
    __shared__ float sKV[NH*DH*DH];
    __shared__ float sKs[NH*DH];
    int tid = threadIdx.x;
    int n = blockIdx.y;
    int l = blockIdx.x * 32 + (tid >> 3);
    int h = tid & 7;
    const float* kvsrc = g_KV + n*NH*DH*DH;
    for (int i = tid; i < NH*DH*DH; i += 256) sKV[i] = kvsrc[i];
    sKs[tid] = g_Ksum[n*256 + tid];
    __syncthreads();
    float q[32];
    const __half* qp = qkv + (size_t)(n*LT + l) * NQKV + h*DH;
#pragma unroll
    for (int d8 = 0; d8 < 4; d8++) {
        uint4 qu = *(const uint4*)(qp + d8*8);
        const __half2* qh = (const __half2*)&qu;
#pragma unroll
        for (int j = 0; j < 4; j++) {
            float2 qf = __half22float2(qh[j]);
            q[d8*8 + 2*j]     = qf.x;
            q[d8*8 + 2*j + 1] = qf.y;
        }
    }
    float z = 0.f;
#pragma unroll
    for (int d = 0; d < 32; d++) z += q[d] * sKs[h*32 + d];
    z = 1.f / (z + 1e-6f);
    __half* op = out + (size_t)(n*LT + l) * CD + h*DH;
#pragma unroll 4
    for (int m = 0; m < 32; m++) {
        const float* kvr = &sKV[(h*32 + m) * 32];
        float s = 0.f;
#pragma unroll
        for (int d = 0; d < 32; d++) s += q[d] * kvr[d];
        op[m] = __float2half(s * z);
    }
}

// warp-per-row LN: x = LN(x+y)*g+b (in place) and xh = half(x)
__global__ void ln_residual(float* __restrict__ x, const float* __restrict__ y,
                            const float* __restrict__ g, const float* __restrict__ b,
                            __half* __restrict__ xh) {
    int row = blockIdx.x * 8 + (threadIdx.x >> 5);
    int lane = threadIdx.x & 31;
    size_t base = (size_t)row * CD + lane * 8;
    float4 xa = *(const float4*)(x + base), xb = *(const float4*)(x + base + 4);
    float4 ya = *(const float4*)(y + base), yb = *(const float4*)(y + base + 4);
    float v[8];
    v[0]=xa.x+ya.x; v[1]=xa.y+ya.y; v[2]=xa.z+ya.z; v[3]=xa.w+ya.w;
    v[4]=xb.x+yb.x; v[5]=xb.y+yb.y; v[6]=xb.z+yb.z; v[7]=xb.w+yb.w;
    float s = 0.f;
#pragma unroll
    for (int i = 0; i < 8; i++) s += v[i];
#pragma unroll
    for (int o = 16; o > 0; o >>= 1) s += __shfl_xor_sync(0xffffffffu, s, o);
    float mean = s * (1.f/256.f);
    float var = 0.f;
#pragma unroll
    for (int i = 0; i < 8; i++) { float d = v[i] - mean; var += d*d; }
#pragma unroll
    for (int o = 16; o > 0; o >>= 1) var += __shfl_xor_sync(0xffffffffu, var, o);
    float rs = rsqrtf(var * (1.f/256.f) + 1e-5f);
    float4 ga = *(const float4*)(g + lane*8), gb = *(const float4*)(g + lane*8 + 4);
    float4 ba = *(const float4*)(b + lane*8), bb = *(const float4*)(b + lane*8 + 4);
    float o0[8];
    o0[0]=(v[0]-mean)*rs*ga.x+ba.x; o0[1]=(v[1]-mean)*rs*ga.y+ba.y;
    o0[2]=(v[2]-mean)*rs*ga.z+ba.z; o0[3]=(v[3]-mean)*rs*ga.w+ba.w;
    o0[4]=(v[4]-mean)*rs*gb.x+bb.x; o0[5]=(v[5]-mean)*rs*gb.y+bb.y;
    o0[6]=(v[6]-mean)*rs*gb.z+bb.z; o0[7]=(v[7]-mean)*rs*gb.w+bb.w;
    float4 w0; w0.x=o0[0]; w0.y=o0[1]; w0.z=o0[2]; w0.w=o0[3];
    float4 w1; w1.x=o0[4]; w1.y=o0[5]; w1.z=o0[6]; w1.w=o0[7];
    *(float4*)(x + base) = w0;
    *(float4*)(x + base + 4) = w1;
    __half2 h0=__floats2half2_rn(o0[0],o0[1]), h1=__floats2half2_rn(o0[2],o0[3]);
    __half2 h2=__floats2half2_rn(o0[4],o0[5]), h3=__floats2half2_rn(o0[6],o0[7]);
    uint4 u; u.x=*(uint32_t*)&h0; u.y=*(uint32_t*)&h1; u.z=*(uint32_t*)&h2; u.w=*(uint32_t*)&h3;
    *(uint4*)(xh + base) = u;
}

__global__ void transpose32(const float* __restrict__ in, float* __restrict__ out,
                            int A, int B) {
    __shared__ float tile[32][33];
    int bx = blockIdx.x * 32;
    int by = blockIdx.y * 32;
    int x = bx + threadIdx.x;
#pragma unroll
    for (int j = 0; j < 32; j += 8)
        tile[threadIdx.y + j][threadIdx.x] = in[(size_t)(by + threadIdx.y + j) * B + x];
    __syncthreads();
    int x2 = by + threadIdx.x;
#pragma unroll
    for (int j = 0; j < 32; j += 8)
        out[(size_t)(bx + threadIdx.y + j) * A + x2] = tile[threadIdx.x][threadIdx.y + j];
}

// ============================================================
extern "C" void kernel_launch(void* const* d_in, const int* in_sizes, int n_in,
                              void* d_out, int out_size) {
    const float* ref = (const float*)d_in[0];
    const float* Wq = (const float*)d_in[1];
    const float* bq = (const float*)d_in[2];
    const float* Wk = (const float*)d_in[3];
    const float* bk = (const float*)d_in[4];
    const float* Wv = (const float*)d_in[5];
    const float* bv = (const float*)d_in[6];
    const float* Wo = (const float*)d_in[7];
    const float* bo = (const float*)d_in[8];
    const float* g1 = (const float*)d_in[9];
    const float* be1 = (const float*)d_in[10];
    const float* W1 = (const float*)d_in[11];
    const float* c1 = (const float*)d_in[12];
    const float* W2 = (const float*)d_in[13];
    const float* c2 = (const float*)d_in[14];
    const float* g2 = (const float*)d_in[15];
    const float* be2 = (const float*)d_in[16];
    float* out = (float*)d_out;

    float *px, *ptmp, *pbqkv;
    __half *pxh, *pah, *phh, *pqkv, *pWqkv, *pWoh, *pW1h, *pW2h;
    cudaGetSymbolAddress((void**)&px, g_x);
    cudaGetSymbolAddress((void**)&ptmp, g_tmp);
    cudaGetSymbolAddress((void**)&pbqkv, g_bqkv);
    cudaGetSymbolAddress((void**)&pxh, g_xh);
    cudaGetSymbolAddress((void**)&pah, g_ah);
    cudaGetSymbolAddress((void**)&phh, g_hh);
    cudaGetSymbolAddress((void**)&pqkv, g_qkvh);
    cudaGetSymbolAddress((void**)&pWqkv, g_Wqkvh);
    cudaGetSymbolAddress((void**)&pWoh, g_Woh);
    cudaGetSymbolAddress((void**)&pW1h, g_W1h);
    cudaGetSymbolAddress((void**)&pW2h, g_W2h);

    // launch 0: all weight conversion in one kernel
    {
        int total = NLAY*NQKV*CD/4 + NLAY*CD*CD/4 + NLAY*FF*CD/4 + NLAY*CD*FF/4 + NLAY*NQKV/4;
        wconv<<<(total + 255)/256, 256>>>(Wq, Wk, Wv, Wo, W1, W2, bq, bk, bv,
                                          pWqkv, pWoh, pW1h, pW2h, pbqkv);
    }

    // launches 1-4: patch embed transpose + fp16 convert
    for (int n = 0; n < NB; n++)
        transpose_in<<<dim3(LT/32, CD/32), dim3(32, 8)>>>(
            ref + (size_t)n * CD * LT,
            px + (size_t)n * LT * CD,
            pxh + (size_t)n * LT * CD);

    dim3 gC(2, MTOT/128);    // N=256
    dim3 gQKV(6, MTOT/128);  // N=768
    dim3 gF(4, MTOT/128);    // N=512

    for (int layer = 0; layer < NLAY; layer++) {
        const __half* Wqkv_l = pWqkv + (size_t)layer*NQKV*CD;
        const float*  bqkv_l = pbqkv + layer*NQKV;
        const __half* Wo_l = pWoh + (size_t)layer*CD*CD;  const float* bo_l = bo + layer*CD;
        const __half* W1_l = pW1h + (size_t)layer*FF*CD;  const float* c1_l = c1 + layer*FF;
        const __half* W2_l = pW2h + (size_t)layer*CD*FF;  const float* c2_l = c2 + layer*CD;
        const float* g1_l = g1 + layer*CD;  const float* be1_l = be1 + layer*CD;
        const float* g2_l = g2 + layer*CD;  const float* be2_l = be2 + layer*CD;

        // launch 5 on first iteration: the QKV GEMM (ncu -s 5 captures this)
        gemm_mma<3,__half><<<gQKV, 256>>>(pxh, Wqkv_l, bqkv_l, pqkv, MTOT, NQKV, CD);

        zero_kv<<<(NB*NH*DH*DH + 255)/256, 256>>>();
        kv_reduce<<<dim3(LT/128, NB*NH), 256>>>(pqkv);
        attn_apply<<<dim3(LT/32, NB), 256>>>(pqkv, pah);

        gemm_mma<0,float><<<gC, 256>>>(pah, Wo_l, bo_l, ptmp, MTOT, CD, CD);
        ln_residual<<<MTOT/8, 256>>>(px, ptmp, g1_l, be1_l, pxh);

        gemm_mma<2,__half><<<gF, 256>>>(pxh, W1_l, c1_l, phh, MTOT, FF, CD);
        gemm_mma<0,float><<<gC, 256>>>(phh, W2_l, c2_l, ptmp, MTOT, CD, FF);
        ln_residual<<<MTOT/8, 256>>>(px, ptmp, g2_l, be2_l, pxh);

        for (int n = 0; n < NB; n++)
            transpose32<<<dim3(CD/32, LT/32), dim3(32, 8)>>>(
                px + (size_t)n * LT * CD,
                out + ((size_t)layer * NB + n) * CD * LT, LT, CD);
    }
}

// round 11
// speedup vs baseline: 1.6044x; 1.6044x over previous
#include <cuda_runtime.h>
#include <cuda_fp16.h>
#include <stdint.h>
#include <math.h>

#define NB 4
#define LT 16384
#define CD 256
#define NH 8
#define DH 32
#define FF 512
#define NLAY 4
#define MTOT (NB*LT)

// ---- fp32 scratch ----
__device__ float g_x[MTOT*CD];
__device__ float g_q[MTOT*CD];
__device__ float g_k[MTOT*CD];
__device__ float g_v[MTOT*CD];
__device__ float g_tmp[MTOT*CD];
__device__ float g_KV[NB*NH*DH*DH];
__device__ float g_Ksum[NB*NH*DH];
// ---- fp16 scratch ----
__device__ __half g_xh[MTOT*CD];
__device__ __half g_ah[MTOT*CD];
__device__ __half g_hh[MTOT*FF];
__device__ __half g_Wqh[NLAY*CD*CD];
__device__ __half g_Wkh[NLAY*CD*CD];
__device__ __half g_Wvh[NLAY*CD*CD];
__device__ __half g_Woh[NLAY*CD*CD];
__device__ __half g_W1h[NLAY*FF*CD];
__device__ __half g_W2h[NLAY*CD*FF];

__device__ __forceinline__ uint32_t smem_u32(const void* p) {
    uint32_t a;
    asm("{ .reg .u64 t; cvta.to.shared.u64 t, %1; cvt.u32.u64 %0, t; }" : "=r"(a) : "l"(p));
    return a;
}
__device__ __forceinline__ void cpa16(uint32_t saddr, const void* g) {
    asm volatile("cp.async.cg.shared.global [%0], [%1], 16;" :: "r"(saddr), "l"(g));
}
#define LDSM4(r0,r1,r2,r3,addr) \
    asm volatile("ldmatrix.sync.aligned.m8n8.x4.shared.b16 {%0,%1,%2,%3}, [%4];" \
        : "=r"(r0),"=r"(r1),"=r"(r2),"=r"(r3) : "r"(addr))
#define MMA16816(c, a, b) \
    asm volatile("mma.sync.aligned.m16n8k16.row.col.f32.f16.f16.f32 " \
        "{%0,%1,%2,%3}, {%4,%5,%6,%7}, {%8,%9}, {%0,%1,%2,%3};" \
        : "+f"((c)[0]),"+f"((c)[1]),"+f"((c)[2]),"+f"((c)[3]) \
        : "r"((a)[0]),"r"((a)[1]),"r"((a)[2]),"r"((a)[3]), "r"((b)[0]),"r"((b)[1]))

__device__ __forceinline__ void st2(float* p, float a, float b) {
    *(float2*)p = make_float2(a, b);
}
__device__ __forceinline__ void st2(__half* p, float a, float b) {
    *(__half2*)p = __floats2half2_rn(a, b);
}

// ============================================================
// HMMA f16 GEMM: C[M,N] = A[M,K] @ B[N,K]^T + bias, ACT 0/1(elu+1)/2(relu)
// 128x128x32 CTA tile, 8 warps (2x4), 3-stage cp.async pipeline, 2 CTAs/SM.
// ============================================================
#define STG 16384
template<int ACT, typename OutT>
__global__ void __launch_bounds__(256, 2)
gemm_mma(const __half* __restrict__ A, const __half* __restrict__ B,
         const float* __restrict__ bias, OutT* __restrict__ C,
         int M, int N, int K)
{
    __shared__ __align__(128) char smem[3*STG];   // 48KB: 3 stages of (A 8KB + B 8KB)
    const int tid = threadIdx.x, wid = tid >> 5, lane = tid & 31;
    const int wm = wid & 1, wn = wid >> 1;
    const int bn = blockIdx.x << 7, bm = blockIdx.y << 7;
    const uint32_t sb = smem_u32(smem);
    const __half* Ag = A + (size_t)bm * K;
    const __half* Bg = B + (size_t)bn * K;
    const int S = K >> 5;

    float acc[4][4][4];
#pragma unroll
    for (int mi = 0; mi < 4; mi++)
#pragma unroll
        for (int ni = 0; ni < 4; ni++)
#pragma unroll
            for (int j = 0; j < 4; j++) acc[mi][ni][j] = 0.f;

    auto load_st = [&](int s) {
        uint32_t dstA = sb + (uint32_t)(s % 3) * STG;
        uint32_t dstB = dstA + 8192;
        int kt = s << 5;
#pragma unroll
        for (int i = 0; i < 2; i++) {
            int c = tid + (i << 8);
            int r = c >> 2, k4 = c & 3;
            uint32_t sw = (uint32_t)(k4 ^ ((r >> 1) & 3));
            cpa16(dstA + r * 64 + (sw << 4), Ag + (size_t)r * K + kt + (k4 << 3));
            cpa16(dstB + r * 64 + (sw << 4), Bg + (size_t)r * K + kt + (k4 << 3));
        }
        asm volatile("cp.async.commit_group;" ::: "memory");
    };

    load_st(0);
    if (S > 1) load_st(1);

    for (int s = 0; s < S; s++) {
        if (s + 1 < S) asm volatile("cp.async.wait_group 1;" ::: "memory");
        else           asm volatile("cp.async.wait_group 0;" ::: "memory");
        __syncthreads();
        if (s + 2 < S) load_st(s + 2);

        uint32_t bA = sb + (uint32_t)(s % 3) * STG;
        uint32_t bB = bA + 8192;
#pragma unroll
        for (int ks = 0; ks < 2; ks++) {
            uint32_t af[4][4], bf[4][2];
#pragma unroll
            for (int mi = 0; mi < 4; mi++) {
                int r = wm * 64 + mi * 16 + (lane & 15);
                int ch = (ks << 1) + (lane >> 4);
                uint32_t ad = bA + r * 64 + (uint32_t)((ch ^ ((r >> 1) & 3)) << 4);
                LDSM4(af[mi][0], af[mi][1], af[mi][2], af[mi][3], ad);
            }
#pragma unroll
            for (int pr = 0; pr < 2; pr++) {
                int n = wn * 32 + pr * 16 + ((lane >> 4) << 3) + (lane & 7);
                int ch = (ks << 1) + ((lane >> 3) & 1);
                uint32_t bd = bB + n * 64 + (uint32_t)((ch ^ ((n >> 1) & 3)) << 4);
                LDSM4(bf[2*pr][0], bf[2*pr][1], bf[2*pr+1][0], bf[2*pr+1][1], bd);
            }
#pragma unroll
            for (int mi = 0; mi < 4; mi++)
#pragma unroll
                for (int ni = 0; ni < 4; ni++)
                    MMA16816(acc[mi][ni], af[mi], bf[ni]);
        }
    }

    // epilogue
    int g = lane >> 2, tg = lane & 3;
#pragma unroll
    for (int ni = 0; ni < 4; ni++) {
        int col = bn + wn * 32 + ni * 8 + tg * 2;
        float b0 = bias[col], b1 = bias[col + 1];
#pragma unroll
        for (int mi = 0; mi < 4; mi++) {
            int r0 = bm + wm * 64 + mi * 16 + g;
            float v00 = acc[mi][ni][0] + b0, v01 = acc[mi][ni][1] + b1;
            float v10 = acc[mi][ni][2] + b0, v11 = acc[mi][ni][3] + b1;
            if (ACT == 1) {
                v00 = (v00 > 0.f) ? (v00 + 1.f) : expf(v00);
                v01 = (v01 > 0.f) ? (v01 + 1.f) : expf(v01);
                v10 = (v10 > 0.f) ? (v10 + 1.f) : expf(v10);
                v11 = (v11 > 0.f) ? (v11 + 1.f) : expf(v11);
            }
            if (ACT == 2) {
                v00 = fmaxf(v00, 0.f); v01 = fmaxf(v01, 0.f);
                v10 = fmaxf(v10, 0.f); v11 = fmaxf(v11, 0.f);
            }
            st2(C + (size_t)r0 * N + col, v00, v01);
            st2(C + (size_t)(r0 + 8) * N + col, v10, v11);
        }
    }
}

// ============================================================
__global__ void f2h(const float* __restrict__ s, __half* __restrict__ d, int n) {
    int i = (blockIdx.x * blockDim.x + threadIdx.x) * 4;
    if (i + 3 < n) {
        float4 f = *(const float4*)(s + i);
        __half2 a = __floats2half2_rn(f.x, f.y);
        __half2 b = __floats2half2_rn(f.z, f.w);
        uint2 u; u.x = *(uint32_t*)&a; u.y = *(uint32_t*)&b;
        *(uint2*)(d + i) = u;
    } else {
        for (; i < n; i++) d[i] = __float2half(s[i]);
    }
}

__global__ void zero_kv() {
    int i = blockIdx.x * blockDim.x + threadIdx.x;
    if (i < NB*NH*DH*DH) g_KV[i] = 0.f;
    if (i < NB*NH*DH)    g_Ksum[i] = 0.f;
}

__global__ void kv_reduce(const float* __restrict__ Kp, const float* __restrict__ Vp) {
    __shared__ float sK[128*32];
    __shared__ float sV[128*32];
    int tid = threadIdx.x;
    int l0 = blockIdx.x * 128;
    int nh = blockIdx.y;
    int n = nh >> 3, h = nh & 7;
    const float* Kbase = Kp + (size_t)(n*LT + l0) * CD + h*DH;
    const float* Vbase = Vp + (size_t)(n*LT + l0) * CD + h*DH;
#pragma unroll
    for (int r = 0; r < 4; r++) {
        int f = tid + 256*r;
        int i = f >> 3;
        int c4 = (f & 7) * 4;
        *(float4*)(&sK[i*32 + c4]) = *(const float4*)(Kbase + (size_t)i*CD + c4);
        *(float4*)(&sV[i*32 + c4]) = *(const float4*)(Vbase + (size_t)i*CD + c4);
    }
    __syncthreads();
    float acc0=0.f, acc1=0.f, acc2=0.f, acc3=0.f;
    int e0 = tid, e1 = tid+256, e2 = tid+512, e3 = tid+768;
    int m0=e0>>5, d0=e0&31, m1=e1>>5, d1=e1&31, m2=e2>>5, d2=e2&31, m3=e3>>5, d3=e3&31;
#pragma unroll 4
    for (int i = 0; i < 128; i++) {
        const float* kr = &sK[i*32];
        const float* vr = &sV[i*32];
        acc0 += vr[m0]*kr[d0]; acc1 += vr[m1]*kr[d1];
        acc2 += vr[m2]*kr[d2]; acc3 += vr[m3]*kr[d3];
    }
    atomicAdd(&g_KV[nh*1024 + e0], acc0);
    atomicAdd(&g_KV[nh*1024 + e1], acc1);
    atomicAdd(&g_KV[nh*1024 + e2], acc2);
    atomicAdd(&g_KV[nh*1024 + e3], acc3);
    if (tid < 32) {
        float s = 0.f;
#pragma unroll 8
        for (int i = 0; i < 128; i++) s += sK[i*32 + tid];
        atomicAdd(&g_Ksum[nh*32 + tid], s);
    }
}

// attn -> fp16 out (GEMM A operand)
__global__ void attn_apply(const float* __restrict__ Qp, __half* __restrict__ out) {
    __shared__ float sKV[NH*DH*DH];
    __shared__ float sKs[NH*DH];
    int tid = threadIdx.x;
    int n = blockIdx.y;
    int l = blockIdx.x * 32 + (tid >> 3);
    int h = tid & 7;
    const float* kvsrc = g_KV + n*NH*DH*DH;
    for (int i = tid; i < NH*DH*DH; i += 256) sKV[i] = kvsrc[i];
    sKs[tid] = g_Ksum[n*256 + tid];
    __syncthreads();
    float q[32];
    const float* qp = Qp + (size_t)(n*LT + l) * CD + h*DH;
#pragma unroll
    for (int d4 = 0; d4 < 8; d4++) {
        float4 t = *(const float4*)(qp + d4*4);
        q[d4*4+0]=t.x; q[d4*4+1]=t.y; q[d4*4+2]=t.z; q[d4*4+3]=t.w;
    }
    float z = 0.f;
#pragma unroll
    for (int d = 0; d < 32; d++) z += q[d] * sKs[h*32 + d];
    z = 1.f / (z + 1e-6f);
    __half* op = out + (size_t)(n*LT + l) * CD + h*DH;
#pragma unroll 4
    for (int m = 0; m < 32; m++) {
        const float* kvr = &sKV[(h*32 + m) * 32];
        float s = 0.f;
#pragma unroll
        for (int d = 0; d < 32; d++) s += q[d] * kvr[d];
        op[m] = __float2half(s * z);
    }
}

// warp-per-row LN: x = LN(x+y)*g+b (in place) and xh = half(x)
__global__ void ln_residual(float* __restrict__ x, const float* __restrict__ y,
                            const float* __restrict__ g, const float* __restrict__ b,
                            __half* __restrict__ xh) {
    int row = blockIdx.x * 8 + (threadIdx.x >> 5);
    int lane = threadIdx.x & 31;
    size_t base = (size_t)row * CD + lane * 8;
    float4 xa = *(const float4*)(x + base), xb = *(const float4*)(x + base + 4);
    float4 ya = *(const float4*)(y + base), yb = *(const float4*)(y + base + 4);
    float v[8];
    v[0]=xa.x+ya.x; v[1]=xa.y+ya.y; v[2]=xa.z+ya.z; v[3]=xa.w+ya.w;
    v[4]=xb.x+yb.x; v[5]=xb.y+yb.y; v[6]=xb.z+yb.z; v[7]=xb.w+yb.w;
    float s = 0.f;
#pragma unroll
    for (int i = 0; i < 8; i++) s += v[i];
#pragma unroll
    for (int o = 16; o > 0; o >>= 1) s += __shfl_xor_sync(0xffffffffu, s, o);
    float mean = s * (1.f/256.f);
    float var = 0.f;
#pragma unroll
    for (int i = 0; i < 8; i++) { float d = v[i] - mean; var += d*d; }
#pragma unroll
    for (int o = 16; o > 0; o >>= 1) var += __shfl_xor_sync(0xffffffffu, var, o);
    float rs = rsqrtf(var * (1.f/256.f) + 1e-5f);
    float4 ga = *(const float4*)(g + lane*8), gb = *(const float4*)(g + lane*8 + 4);
    float4 ba = *(const float4*)(b + lane*8), bb = *(const float4*)(b + lane*8 + 4);
    float o0[8];
    o0[0]=(v[0]-mean)*rs*ga.x+ba.x; o0[1]=(v[1]-mean)*rs*ga.y+ba.y;
    o0[2]=(v[2]-mean)*rs*ga.z+ba.z; o0[3]=(v[3]-mean)*rs*ga.w+ba.w;
    o0[4]=(v[4]-mean)*rs*gb.x+bb.x; o0[5]=(v[5]-mean)*rs*gb.y+bb.y;
    o0[6]=(v[6]-mean)*rs*gb.z+bb.z; o0[7]=(v[7]-mean)*rs*gb.w+bb.w;
    float4 w0; w0.x=o0[0]; w0.y=o0[1]; w0.z=o0[2]; w0.w=o0[3];
    float4 w1; w1.x=o0[4]; w1.y=o0[5]; w1.z=o0[6]; w1.w=o0[7];
    *(float4*)(x + base) = w0;
    *(float4*)(x + base + 4) = w1;
    __half2 h0=__floats2half2_rn(o0[0],o0[1]), h1=__floats2half2_rn(o0[2],o0[3]);
    __half2 h2=__floats2half2_rn(o0[4],o0[5]), h3=__floats2half2_rn(o0[6],o0[7]);
    uint4 u; u.x=*(uint32_t*)&h0; u.y=*(uint32_t*)&h1; u.z=*(uint32_t*)&h2; u.w=*(uint32_t*)&h3;
    *(uint4*)(xh + base) = u;
}

// input transpose [CD x LT] -> x [LT x CD] (fp32) + xh (fp16)
__global__ void transpose_in(const float* __restrict__ in, float* __restrict__ out,
                             __half* __restrict__ outh) {
    __shared__ float tile[32][33];
    int bx = blockIdx.x * 32;   // over LT
    int by = blockIdx.y * 32;   // over CD
    int x = bx + threadIdx.x;
#pragma unroll
    for (int j = 0; j < 32; j += 8)
        tile[threadIdx.y + j][threadIdx.x] = in[(size_t)(by + threadIdx.y + j) * LT + x];
    __syncthreads();
    int x2 = by + threadIdx.x;
#pragma unroll
    for (int j = 0; j < 32; j += 8) {
        float v = tile[threadIdx.x][threadIdx.y + j];
        size_t o = (size_t)(bx + threadIdx.y + j) * CD + x2;
        out[o] = v;
        outh[o] = __float2half(v);
    }
}

__global__ void transpose32(const float* __restrict__ in, float* __restrict__ out,
                            int A, int B) {
    __shared__ float tile[32][33];
    int bx = blockIdx.x * 32;
    int by = blockIdx.y * 32;
    int x = bx + threadIdx.x;
#pragma unroll
    for (int j = 0; j < 32; j += 8)
        tile[threadIdx.y + j][threadIdx.x] = in[(size_t)(by + threadIdx.y + j) * B + x];
    __syncthreads();
    int x2 = by + threadIdx.x;
#pragma unroll
    for (int j = 0; j < 32; j += 8)
        out[(size_t)(bx + threadIdx.y + j) * A + x2] = tile[threadIdx.x][threadIdx.y + j];
}

// ============================================================
extern "C" void kernel_launch(void* const* d_in, const int* in_sizes, int n_in,
                              void* d_out, int out_size) {
    const float* ref = (const float*)d_in[0];
    const float* Wq = (const float*)d_in[1];
    const float* bq = (const float*)d_in[2];
    const float* Wk = (const float*)d_in[3];
    const float* bk = (const float*)d_in[4];
    const float* Wv = (const float*)d_in[5];
    const float* bv = (const float*)d_in[6];
    const float* Wo = (const float*)d_in[7];
    const float* bo = (const float*)d_in[8];
    const float* g1 = (const float*)d_in[9];
    const float* be1 = (const float*)d_in[10];
    const float* W1 = (const float*)d_in[11];
    const float* c1 = (const float*)d_in[12];
    const float* W2 = (const float*)d_in[13];
    const float* c2 = (const float*)d_in[14];
    const float* g2 = (const float*)d_in[15];
    const float* be2 = (const float*)d_in[16];
    float* out = (float*)d_out;

    float *px, *pq, *pk, *pv, *ptmp;
    __half *pxh, *pah, *phh, *pWqh, *pWkh, *pWvh, *pWoh, *pW1h, *pW2h;
    cudaGetSymbolAddress((void**)&px, g_x);
    cudaGetSymbolAddress((void**)&pq, g_q);
    cudaGetSymbolAddress((void**)&pk, g_k);
    cudaGetSymbolAddress((void**)&pv, g_v);
    cudaGetSymbolAddress((void**)&ptmp, g_tmp);
    cudaGetSymbolAddress((void**)&pxh, g_xh);
    cudaGetSymbolAddress((void**)&pah, g_ah);
    cudaGetSymbolAddress((void**)&phh, g_hh);
    cudaGetSymbolAddress((void**)&pWqh, g_Wqh);
    cudaGetSymbolAddress((void**)&pWkh, g_Wkh);
    cudaGetSymbolAddress((void**)&pWvh, g_Wvh);
    cudaGetSymbolAddress((void**)&pWoh, g_Woh);
    cudaGetSymbolAddress((void**)&pW1h, g_W1h);
    cudaGetSymbolAddress((void**)&pW2h, g_W2h);

    // weight conversion fp32 -> fp16
    int wn = NLAY*CD*CD;
    f2h<<<(wn/4 + 255)/256, 256>>>(Wq, pWqh, wn);
    f2h<<<(wn/4 + 255)/256, 256>>>(Wk, pWkh, wn);
    f2h<<<(wn/4 + 255)/256, 256>>>(Wv, pWvh, wn);
    f2h<<<(wn/4 + 255)/256, 256>>>(Wo, pWoh, wn);
    int wf = NLAY*FF*CD;
    f2h<<<(wf/4 + 255)/256, 256>>>(W1, pW1h, wf);
    f2h<<<(wf/4 + 255)/256, 256>>>(W2, pW2h, wf);

    // patch embed: x[n,l,c] = ref[n,c,l] (fused fp32+fp16 output)
    for (int n = 0; n < NB; n++)
        transpose_in<<<dim3(LT/32, CD/32), dim3(32, 8)>>>(
            ref + (size_t)n * CD * LT,
            px + (size_t)n * LT * CD,
            pxh + (size_t)n * LT * CD);

    dim3 gC(2, MTOT/128);   // N=256
    dim3 gF(4, MTOT/128);   // N=512

    for (int layer = 0; layer < NLAY; layer++) {
        const __half* Wq_l = pWqh + (size_t)layer*CD*CD;  const float* bq_l = bq + layer*CD;
        const __half* Wk_l = pWkh + (size_t)layer*CD*CD;  const float* bk_l = bk + layer*CD;
        const __half* Wv_l = pWvh + (size_t)layer*CD*CD;  const float* bv_l = bv + layer*CD;
        const __half* Wo_l = pWoh + (size_t)layer*CD*CD;  const float* bo_l = bo + layer*CD;
        const __half* W1_l = pW1h + (size_t)layer*FF*CD;  const float* c1_l = c1 + layer*FF;
        const __half* W2_l = pW2h + (size_t)layer*CD*FF;  const float* c2_l = c2 + layer*CD;
        const float* g1_l = g1 + layer*CD;  const float* be1_l = be1 + layer*CD;
        const float* g2_l = g2 + layer*CD;  const float* be2_l = be2 + layer*CD;

        gemm_mma<1,float><<<gC, 256>>>(pxh, Wq_l, bq_l, pq, MTOT, CD, CD);
        gemm_mma<1,float><<<gC, 256>>>(pxh, Wk_l, bk_l, pk, MTOT, CD, CD);
        gemm_mma<0,float><<<gC, 256>>>(pxh, Wv_l, bv_l, pv, MTOT, CD, CD);

        zero_kv<<<(NB*NH*DH*DH + 255)/256, 256>>>();
        kv_reduce<<<dim3(LT/128, NB*NH), 256>>>(pk, pv);
        attn_apply<<<dim3(LT/32, NB), 256>>>(pq, pah);

        gemm_mma<0,float><<<gC, 256>>>(pah, Wo_l, bo_l, ptmp, MTOT, CD, CD);
        ln_residual<<<MTOT/8, 256>>>(px, ptmp, g1_l, be1_l, pxh);

        gemm_mma<2,__half><<<gF, 256>>>(pxh, W1_l, c1_l, phh, MTOT, FF, CD);
        gemm_mma<0,float><<<gC, 256>>>(phh, W2_l, c2_l, ptmp, MTOT, CD, FF);
        ln_residual<<<MTOT/8, 256>>>(px, ptmp, g2_l, be2_l, pxh);

        for (int n = 0; n < NB; n++)
            transpose32<<<dim3(CD/32, LT/32), dim3(32, 8)>>>(
                px + (size_t)n * LT * CD,
                out + ((size_t)layer * NB + n) * CD * LT, LT, CD);
    }
}